// round 4
// baseline (speedup 1.0000x reference)
#include <cuda_runtime.h>

#define HH 96
#define WW 128
#define CC 21
#define RR 14
#define ITERS 5
#define NBLK 96
#define NTHR 672           // 21 warps: warp = channel, lane = x-quad
#define PH (HH + 2*RR)     // 124 padded rows
#define SPW 160            // padded prob-row floats: 14 | 128 | 14 | 4 spare

// double-buffered blur-x output, [c][padded_row][x-quad] as float4, zero-padded rows
__device__ float4 g_t[2][CC][PH*32];
__device__ unsigned g_barcnt[ITERS];

// cumulative-ticket grid barrier: replay-safe (each replay adds exactly NBLK
// arrivals per counter), wrap-safe (signed compare).
__device__ __forceinline__ void gridbar(int k) {
    __syncthreads();
    __threadfence();
    if (threadIdx.x == 0) {
        unsigned t = atomicAdd(&g_barcnt[k], 1u);
        unsigned target = t - (t % (unsigned)NBLK) + (unsigned)NBLK;
        volatile unsigned* pc = &g_barcnt[k];
        while ((int)(*pc - target) < 0) { }
        __threadfence();
    }
    __syncthreads();
}

__global__ void __launch_bounds__(NTHR, 1) crf_persistent(
    const float* __restrict__ un, const float* __restrict__ ws,
    const float* __restrict__ wb, const float* __restrict__ comp,
    float* __restrict__ out)
{
    // exp(-d*d/18) taps as literals -> FFMA-imm (rt=1)
    const float w[15] = {
        1.0f, 0.9459594f, 0.8007374f, 0.6065307f, 0.4111123f,
        0.2493522f, 0.1353353f, 0.0657285f, 0.0285655f, 0.0111090f,
        0.0038659f, 0.0012039f, 0.00033546f, 0.00008365f, 0.00001866f };

    __shared__ float  sp[CC][SPW];        // softmax probs, zero-padded in x
    __shared__ float4 sv[CC][32];         // exp values, then blurred s values
    __shared__ float  sA[CC][CC];         // A[c2][c] = compat @ (Ws+Wb)

    const int tid = threadIdx.x;
    const int c   = tid >> 5;             // warp = channel 0..20
    const int l   = tid & 31;             // lane = x-quad, pixels 4l..4l+3
    const int y   = blockIdx.x;

    // ---- one-time init ----
    if (l < CC) {                          // warp c computes A row c
        float a = 0.f;
        #pragma unroll
        for (int k = 0; k < CC; k++)
            a += comp[c*CC + k] * (ws[k*CC + l] + wb[k*CC + l]);
        sA[c][l] = a;
    }
    if (l < RR) { sp[c][l] = 0.f; sp[c][RR + WW + l] = 0.f; }
    // zero g_t row padding (grid-strided, float4 granularity)
    {
        float4 z = {0.f, 0.f, 0.f, 0.f};
        int total = 2*CC*2*RR*32;
        for (int idx = blockIdx.x*NTHR + tid; idx < total; idx += NBLK*NTHR) {
            int ll = idx & 31;
            int r  = (idx >> 5) % (2*RR);
            int cc = ((idx >> 5) / (2*RR)) % CC;
            int b  = (idx >> 5) / (2*RR) / CC;
            int pr = (r < RR) ? r : r + HH;          // rows [0,14) and [110,124)
            g_t[b][cc][pr*32 + ll] = z;
        }
    }
    // normalizers (truncated sums matching the blur truncation)
    float4 nxi;
    {
        float s[4];
        #pragma unroll
        for (int j = 0; j < 4; j++) {
            int x = 4*l + j; float t = 0.f;
            #pragma unroll
            for (int d = -RR; d <= RR; d++) {
                int ad = d < 0 ? -d : d;
                if ((unsigned)(x + d) < WW) t += w[ad];
            }
            s[j] = 1.0f / t;
        }
        nxi.x = s[0]; nxi.y = s[1]; nxi.z = s[2]; nxi.w = s[3];
    }
    float ny = 0.f;
    #pragma unroll
    for (int d = -RR; d <= RR; d++) {
        int ad = d < 0 ? -d : d;
        if ((unsigned)(y + d) < HH) ny += w[ad];
    }
    const float nyi = 1.0f / ny;

    // unaries -> registers (q never touches memory)
    float4 u4, q4;
    u4.x = un[(y*WW + 4*l + 0)*CC + c];
    u4.y = un[(y*WW + 4*l + 1)*CC + c];
    u4.z = un[(y*WW + 4*l + 2)*CC + c];
    u4.w = un[(y*WW + 4*l + 3)*CC + c];
    q4 = u4;
    __syncthreads();

    // ---- CRF iterations ----
    for (int it = 0; it < ITERS; it++) {
        float4* tb = &g_t[it & 1][0][0];

        // softmax over channels (no max-sub: q stays far below exp overflow)
        float4 e4;
        e4.x = __expf(q4.x); e4.y = __expf(q4.y);
        e4.z = __expf(q4.z); e4.w = __expf(q4.w);
        sv[c][l] = e4;
        __syncthreads();
        float4 sm = {0.f, 0.f, 0.f, 0.f};
        #pragma unroll
        for (int c2 = 0; c2 < CC; c2++) {
            float4 v = sv[c2][l];
            sm.x += v.x; sm.y += v.y; sm.z += v.z; sm.w += v.w;
        }
        sp[c][RR + 4*l + 0] = e4.x * __frcp_rn(sm.x);
        sp[c][RR + 4*l + 1] = e4.y * __frcp_rn(sm.y);
        sp[c][RR + 4*l + 2] = e4.z * __frcp_rn(sm.z);
        sp[c][RR + 4*l + 3] = e4.w * __frcp_rn(sm.w);
        __syncthreads();

        // blur-x: aligned 32-float window via 8 LDS.128, taps as immediates
        float win[32];
        {
            const float4* rowp = (const float4*)&sp[c][0];
            #pragma unroll
            for (int k = 0; k < 8; k++) {
                float4 v = rowp[l + k];
                win[4*k+0] = v.x; win[4*k+1] = v.y;
                win[4*k+2] = v.z; win[4*k+3] = v.w;
            }
        }
        float4 acc = {0.f, 0.f, 0.f, 0.f};
        #pragma unroll
        for (int dd = 0; dd <= 28; dd++) {
            float cw = w[dd < RR ? RR - dd : dd - RR];
            acc.x += cw * win[dd];
            acc.y += cw * win[dd + 1];
            acc.z += cw * win[dd + 2];
            acc.w += cw * win[dd + 3];
        }
        acc.x *= nxi.x; acc.y *= nxi.y; acc.z *= nxi.z; acc.w *= nxi.w;
        tb[c*(PH*32) + (y + RR)*32 + l] = acc;   // STG.128

        gridbar(it);   // all rows' blur-x visible in L2

        // blur-y: 29 x LDG.128 from other blocks' rows (padded: y..y+28)
        float4 a4 = {0.f, 0.f, 0.f, 0.f};
        const float4* col = &tb[c*(PH*32) + y*32 + l];
        #pragma unroll
        for (int dd = 0; dd <= 28; dd++) {
            float4 v = __ldcg(&col[dd*32]);
            float cw = w[dd < RR ? RR - dd : dd - RR];
            a4.x += cw * v.x; a4.y += cw * v.y;
            a4.z += cw * v.z; a4.w += cw * v.w;
        }
        a4.x *= nyi; a4.y *= nyi; a4.z *= nyi; a4.w *= nyi;
        sv[c][l] = a4;
        __syncthreads();

        // message matvec: warp c computes m[c] = sum_c' A[c][c'] * s[c']
        float4 m4 = {0.f, 0.f, 0.f, 0.f};
        #pragma unroll
        for (int c2 = 0; c2 < CC; c2++) {
            float  a  = sA[c][c2];     // LDS broadcast
            float4 s4 = sv[c2][l];
            m4.x += a * s4.x; m4.y += a * s4.y;
            m4.z += a * s4.z; m4.w += a * s4.w;
        }
        if (it < ITERS-1) {
            q4.x = u4.x - m4.x; q4.y = u4.y - m4.y;
            q4.z = u4.z - m4.z; q4.w = u4.w - m4.w;
            __syncthreads();   // protect sv reads from next iter's exp writes
        } else {
            // out[0, x, y, c] layout: (1, W, H, C)
            out[((4*l + 0)*HH + y)*CC + c] = u4.x - m4.x;
            out[((4*l + 1)*HH + y)*CC + c] = u4.y - m4.y;
            out[((4*l + 2)*HH + y)*CC + c] = u4.z - m4.z;
            out[((4*l + 3)*HH + y)*CC + c] = u4.w - m4.w;
        }
    }
}

extern "C" void kernel_launch(void* const* d_in, const int* in_sizes, int n_in,
                              void* d_out, int out_size) {
    const float* un   = (const float*)d_in[0];
    // d_in[1] (rgb) is dead: reference uses spatial_out for both message terms
    const float* ws   = (const float*)d_in[2];
    const float* wb   = (const float*)d_in[3];
    const float* comp = (const float*)d_in[4];
    crf_persistent<<<NBLK, NTHR>>>(un, ws, wb, comp, (float*)d_out);
}